// round 1
// baseline (speedup 1.0000x reference)
#include <cuda_runtime.h>

#define BATCH 4
#define NPTS 8192
#define TILE_Q 1024
#define TILE_T 1024
#define THREADS 256
#define QPT 4   // TILE_Q / THREADS

// Cross-block min scratch: order-preserving uint keys. 2*4*8192 = 64K entries.
__device__ unsigned g_minkey[2 * BATCH * NPTS];

__device__ __forceinline__ unsigned long long pack2(float a, float b) {
    unsigned long long r;
    asm("mov.b64 %0, {%1, %2};" : "=l"(r) : "f"(a), "f"(b));
    return r;
}
__device__ __forceinline__ void unpack2(unsigned long long v, float& a, float& b) {
    asm("mov.b64 {%0, %1}, %2;" : "=f"(a), "=f"(b) : "l"(v));
}
// Packed dual-FMA: 2 fp32 lanes per instruction (FFMA2) — 2x fp32 pipe rate on sm_103a.
__device__ __forceinline__ unsigned long long fma2(unsigned long long a,
                                                   unsigned long long b,
                                                   unsigned long long c) {
    unsigned long long d;
    asm("fma.rn.f32x2 %0, %1, %2, %3;" : "=l"(d) : "l"(a), "l"(b), "l"(c));
    return d;
}
// Monotone float -> uint map (valid for negatives too) so atomicMin(uint) == float min.
__device__ __forceinline__ unsigned fkey(float f) {
    unsigned u = __float_as_uint(f);
    return (u & 0x80000000u) ? ~u : (u | 0x80000000u);
}
__device__ __forceinline__ float finv(unsigned k) {
    return __uint_as_float((k & 0x80000000u) ? (k & 0x7FFFFFFFu) : ~k);
}

__global__ void init_kernel(float* out) {
    int i = blockIdx.x * blockDim.x + threadIdx.x;
    if (i < 2 * BATCH * NPTS) g_minkey[i] = 0xFFFFFFFFu;  // key(+huge)
    if (i == 0) out[0] = 0.0f;
}

__global__ __launch_bounds__(THREADS)
void chamfer_main(const float* __restrict__ p1, const float* __restrict__ p2) {
    const int dir = blockIdx.z;                 // 0: q=p1,t=p2 ; 1: q=p2,t=p1
    const float* __restrict__ Q = dir ? p2 : p1;
    const float* __restrict__ T = dir ? p1 : p2;
    const int b  = blockIdx.y;
    const int qt = blockIdx.x & ((NPTS / TILE_Q) - 1);
    const int ts = blockIdx.x / (NPTS / TILE_Q);

    // Precomputed target tile: -2*y and |y|^2, SoA for packed loads.
    __shared__ __align__(16) float s_n0[TILE_T];
    __shared__ __align__(16) float s_n1[TILE_T];
    __shared__ __align__(16) float s_n2[TILE_T];
    __shared__ __align__(16) float s_c [TILE_T];

    const float* tb = T + ((size_t)b * NPTS + (size_t)ts * TILE_T) * 3;
    for (int i = threadIdx.x; i < TILE_T; i += THREADS) {
        float y0 = tb[3 * i], y1 = tb[3 * i + 1], y2 = tb[3 * i + 2];
        s_n0[i] = -2.0f * y0;
        s_n1[i] = -2.0f * y1;
        s_n2[i] = -2.0f * y2;
        s_c[i]  = y0 * y0 + y1 * y1 + y2 * y2;
    }
    __syncthreads();

    // Each thread owns QPT query points (duplicated into both f32x2 halves).
    unsigned long long qx[QPT], qy[QPT], qz[QPT];
    float mn[QPT];
    const int qbase = qt * TILE_Q + threadIdx.x;
#pragma unroll
    for (int k = 0; k < QPT; k++) {
        const float* qp = Q + ((size_t)b * NPTS + qbase + k * THREADS) * 3;
        float x0 = qp[0], x1 = qp[1], x2 = qp[2];
        qx[k] = pack2(x0, x0);
        qy[k] = pack2(x1, x1);
        qz[k] = pack2(x2, x2);
        mn[k] = 3.4e38f;
    }

    const unsigned long long* s0 = (const unsigned long long*)s_n0;
    const unsigned long long* s1 = (const unsigned long long*)s_n1;
    const unsigned long long* s2 = (const unsigned long long*)s_n2;
    const unsigned long long* sc = (const unsigned long long*)s_c;

    // 2 targets per iteration via packed FMA; loads are warp-uniform -> smem broadcast.
#pragma unroll 4
    for (int j = 0; j < TILE_T / 2; j++) {
        unsigned long long n0 = s0[j], n1 = s1[j], n2 = s2[j], cc = sc[j];
#pragma unroll
        for (int k = 0; k < QPT; k++) {
            unsigned long long t = fma2(qx[k], n0, cc);
            t = fma2(qy[k], n1, t);
            t = fma2(qz[k], n2, t);
            float lo, hi;
            unpack2(t, lo, hi);
            mn[k] = fminf(mn[k], fminf(lo, hi));
        }
    }

    unsigned* gm = g_minkey + ((size_t)dir * BATCH + b) * NPTS;
#pragma unroll
    for (int k = 0; k < QPT; k++)
        atomicMin(&gm[qbase + k * THREADS], fkey(mn[k]));
}

__global__ __launch_bounds__(256)
void chamfer_finish(const float* __restrict__ p1, const float* __restrict__ p2,
                    float* __restrict__ out) {
    const int gid = blockIdx.x * blockDim.x + threadIdx.x;  // over 2*BATCH*NPTS
    const int dir = gid / (BATCH * NPTS);
    const int rem = gid - dir * (BATCH * NPTS);
    const float* Q = dir ? p2 : p1;
    const float* qp = Q + (size_t)rem * 3;
    float x0 = qp[0], x1 = qp[1], x2 = qp[2];
    float v = x0 * x0 + x1 * x1 + x2 * x2 + finv(g_minkey[gid]);

    // warp reduce
#pragma unroll
    for (int o = 16; o; o >>= 1) v += __shfl_down_sync(0xffffffffu, v, o);
    __shared__ float sred[8];
    if ((threadIdx.x & 31) == 0) sred[threadIdx.x >> 5] = v;
    __syncthreads();
    if (threadIdx.x < 32) {
        float w = (threadIdx.x < 8) ? sred[threadIdx.x] : 0.0f;
#pragma unroll
        for (int o = 4; o; o >>= 1) w += __shfl_down_sync(0xffffffffu, w, o);
        if (threadIdx.x == 0) atomicAdd(out, w);
    }
}

extern "C" void kernel_launch(void* const* d_in, const int* in_sizes, int n_in,
                              void* d_out, int out_size) {
    const float* p1 = (const float*)d_in[0];
    const float* p2 = (const float*)d_in[1];
    float* out = (float*)d_out;

    init_kernel<<<(2 * BATCH * NPTS + 255) / 256, 256>>>(out);

    dim3 grid((NPTS / TILE_Q) * (NPTS / TILE_T), BATCH, 2);  // (64, 4, 2) = 512 blocks
    chamfer_main<<<grid, THREADS>>>(p1, p2);

    chamfer_finish<<<(2 * BATCH * NPTS) / 256, 256>>>(p1, p2, out);
}